// round 13
// baseline (speedup 1.0000x reference)
#include <cuda_runtime.h>
#include <cstdint>

#define N_VOX   262144
#define M_PAIRS 131072
#define K_OFF   27
#define C       32
#define CPAD    36        // row stride in floats (144B; 16B-aligned, bank-shifted)

// ---------------------------------------------------------------------------
// Kernel 1: out[n][c] = bias[c]  (bias add commutes with the scatter-adds)
// ---------------------------------------------------------------------------
__global__ void bias_init_kernel(float* __restrict__ out,
                                 const float* __restrict__ bias)
{
    int t = blockIdx.x * blockDim.x + threadIdx.x;
    const int total4 = N_VOX * (C / 4);
    if (t < total4) {
        const float4* b4 = (const float4*)bias;
        float4* o4 = (float4*)out;
        o4[t] = b4[t & 7];
    }
}

// ---------------------------------------------------------------------------
// Kernel 2: multi-tile block, double-buffered TMA bulk gather -> smem ->
//           input-packed f32x2 GEMM (R9/R12 scheme) -> red.v2 scatter.
//
//   Each block processes TILES=8 tiles of 128 pairs, all from the same k:
//   weights are loaded ONCE per block (8x amortization), and the TMA gather
//   for tile t+1 is issued before waiting on tile t (depth-2 pipeline), so
//   the gather round-trip is hidden behind compute.
//   Compute: 16-lane half owns one pair; lane covers channels (2c, 2c+1);
//   row read as ulonglong2 (LDS.128 -> packed f32x2 input pairs) feeding
//   fma.rn.f32x2 directly. Scatter: red.global.add.v2.f32 (contiguous
//   128B per pair).
// ---------------------------------------------------------------------------
#define THREADS          128
#define WARPS_PER_BLOCK  4
#define PAIRS_PER_BLOCK  128
#define PAIRS_PER_WARP   32
#define STEPS            16            // 2 pairs per step (one per half-warp)
#define TILES            8             // tiles (of 128 pairs) per block

__device__ __forceinline__ uint32_t smem_u32(const void* p) {
    uint32_t a;
    asm("{ .reg .u64 t; cvta.to.shared.u64 t, %1; cvt.u32.u64 %0, t; }"
        : "=r"(a) : "l"(p));
    return a;
}

__device__ __forceinline__ void mbar_wait(uint32_t mbar_a, uint32_t parity) {
    uint32_t done;
    asm volatile(
        "{\n\t"
        ".reg .pred p;\n\t"
        "mbarrier.try_wait.parity.acquire.cta.shared::cta.b64 p, [%1], %2;\n\t"
        "selp.b32 %0, 1, 0, p;\n\t"
        "}"
        : "=r"(done) : "r"(mbar_a), "r"(parity) : "memory");
    if (!done) {
        asm volatile(
            "{\n\t"
            ".reg .pred P1;\n\t"
            "WAIT_LOOP_%=:\n\t"
            "mbarrier.try_wait.parity.acquire.cta.shared::cta.b64 P1, [%0], %1, 0x989680;\n\t"
            "@P1 bra.uni WAIT_DONE_%=;\n\t"
            "bra.uni WAIT_LOOP_%=;\n\t"
            "WAIT_DONE_%=:\n\t"
            "}"
            :: "r"(mbar_a), "r"(parity) : "memory");
    }
}

__global__ __launch_bounds__(THREADS)
void scatter_gemm_kernel(const float* __restrict__ input,
                         const float* __restrict__ kernel,
                         const int*   __restrict__ in_map,
                         const int*   __restrict__ out_map,
                         float*       __restrict__ out)
{
    __shared__ float srow[2][PAIRS_PER_BLOCK][CPAD];   // 36 KB ring of rows
    __shared__ alignas(8) unsigned long long mbar[2];

    const int k     = blockIdx.y;
    const int lane  = threadIdx.x & 31;
    const int warp  = threadIdx.x >> 5;
    const int half  = lane >> 4;          // which pair of the step
    const int chalf = lane & 15;          // covers channels 2*chalf, 2*chalf+1

    const int* im = in_map  + k * M_PAIRS;
    const int* om = out_map + k * M_PAIRS;
    const int base0 = blockIdx.x * (PAIRS_PER_BLOCK * TILES);

    const uint32_t mbar_a0 = smem_u32(&mbar[0]);
    const uint32_t mbar_a1 = smem_u32(&mbar[1]);

    if (threadIdx.x == 0) {
        asm volatile("mbarrier.init.shared.b64 [%0], 1;" :: "r"(mbar_a0) : "memory");
        asm volatile("mbarrier.init.shared.b64 [%0], 1;" :: "r"(mbar_a1) : "memory");
    }
    __syncthreads();

    // ---- Prologue: issue gather for tile 0 into buffer 0.
    {
        if (threadIdx.x == 0)
            asm volatile("mbarrier.arrive.expect_tx.shared.b64 _, [%0], %1;"
                         :: "r"(mbar_a0), "r"(PAIRS_PER_BLOCK * C * 4) : "memory");
        const int irow = __ldg(im + base0 + threadIdx.x);
        const float* src = input + (size_t)irow * C;
        asm volatile(
            "cp.async.bulk.shared::cta.global.mbarrier::complete_tx::bytes "
            "[%0], [%1], %2, [%3];"
            :: "r"(smem_u32(&srow[0][threadIdx.x][0])), "l"(src),
               "r"(C * 4), "r"(mbar_a0) : "memory");
    }

    // ---- Weights (loaded once per block, overlap with tile-0 gather):
    //   wA[i] = (W[2i][c0], W[2i+1][c0]),  wB[i] = (W[2i][c1], W[2i+1][c1])
    const float* Wk = kernel + k * C * C;
    unsigned long long wA[C / 2], wB[C / 2];
    #pragma unroll
    for (int i = 0; i < C / 2; i++) {
        float2 f = __ldg((const float2*)(Wk + (2 * i)     * C) + chalf);
        float2 g = __ldg((const float2*)(Wk + (2 * i + 1) * C) + chalf);
        asm("mov.b64 %0, {%1, %2};" : "=l"(wA[i]) : "f"(f.x), "f"(g.x));
        asm("mov.b64 %0, {%1, %2};" : "=l"(wB[i]) : "f"(f.y), "f"(g.y));
    }

    const int pbase = warp * PAIRS_PER_WARP;

    for (int t = 0; t < TILES; t++) {
        const int buf  = t & 1;
        const int tbase = base0 + t * PAIRS_PER_BLOCK;

        // ---- Issue gather for tile t+1 into the other buffer.
        //      Safe: that buffer's readers finished at the sync ending t-1.
        if (t + 1 < TILES) {
            const int nbuf = (t + 1) & 1;
            const uint32_t nmb = nbuf ? mbar_a1 : mbar_a0;
            if (threadIdx.x == 0)
                asm volatile("mbarrier.arrive.expect_tx.shared.b64 _, [%0], %1;"
                             :: "r"(nmb), "r"(PAIRS_PER_BLOCK * C * 4) : "memory");
            const int irow = __ldg(im + tbase + PAIRS_PER_BLOCK + threadIdx.x);
            const float* src = input + (size_t)irow * C;
            asm volatile(
                "cp.async.bulk.shared::cta.global.mbarrier::complete_tx::bytes "
                "[%0], [%1], %2, [%3];"
                :: "r"(smem_u32(&srow[nbuf][threadIdx.x][0])), "l"(src),
                   "r"(C * 4), "r"(nmb) : "memory");
        }

        // ---- Wait for tile t's rows. Buffer buf's use index is t>>1.
        mbar_wait(buf ? mbar_a1 : mbar_a0, (t >> 1) & 1);

        // ---- Compute + scatter (R9/R12 scheme).
        #pragma unroll 4
        for (int s = 0; s < STEPS; s++) {
            const int pw   = 2 * s + half;
            const int orow = __ldg(om + tbase + pbase + pw);

            const ulonglong2* r2 = (const ulonglong2*)&srow[buf][pbase + pw][0];

            unsigned long long accA = 0ULL, accB = 0ULL;
            #pragma unroll
            for (int j = 0; j < C / 4; j++) {
                ulonglong2 a = r2[j];           // LDS.128, 2 distinct rows/warp
                asm("fma.rn.f32x2 %0, %1, %2, %0;" : "+l"(accA) : "l"(a.x), "l"(wA[2 * j]));
                asm("fma.rn.f32x2 %0, %1, %2, %0;" : "+l"(accA) : "l"(a.y), "l"(wA[2 * j + 1]));
                asm("fma.rn.f32x2 %0, %1, %2, %0;" : "+l"(accB) : "l"(a.x), "l"(wB[2 * j]));
                asm("fma.rn.f32x2 %0, %1, %2, %0;" : "+l"(accB) : "l"(a.y), "l"(wB[2 * j + 1]));
            }
            float a0, a1, b0, b1;
            asm("mov.b64 {%0, %1}, %2;" : "=f"(a0), "=f"(a1) : "l"(accA));
            asm("mov.b64 {%0, %1}, %2;" : "=f"(b0), "=f"(b1) : "l"(accB));
            const float c0 = a0 + a1;
            const float c1 = b0 + b1;

            float* dst = out + (size_t)orow * C + 2 * chalf;   // 8B aligned
            asm volatile("red.global.add.v2.f32 [%0], {%1, %2};"
                         :: "l"(dst), "f"(c0), "f"(c1) : "memory");
        }

        // ---- All warps done reading buf before it is refilled at t+2.
        __syncthreads();
    }
}

// ---------------------------------------------------------------------------
// Launch
// ---------------------------------------------------------------------------
extern "C" void kernel_launch(void* const* d_in, const int* in_sizes, int n_in,
                              void* d_out, int out_size)
{
    const float* input   = (const float*)d_in[0];
    const float* kernelw = (const float*)d_in[1];
    const float* bias    = (const float*)d_in[2];
    const int*   in_map  = (const int*)  d_in[3];
    const int*   out_map = (const int*)  d_in[4];
    float*       out     = (float*)d_out;

    const int total4 = N_VOX * (C / 4);
    bias_init_kernel<<<(total4 + 255) / 256, 256>>>(out, bias);

    dim3 grid(M_PAIRS / (PAIRS_PER_BLOCK * TILES), K_OFF);
    scatter_gemm_kernel<<<grid, THREADS>>>(input, kernelw, in_map, out_map, out);
}